// round 8
// baseline (speedup 1.0000x reference)
#include <cuda_runtime.h>
#include <cuda_bf16.h>
#include <math.h>
#include <cstdint>

// Problem constants
#define Nn 4
#define Cc 64
#define Hh 128
#define Ww 128
#define HW (Hh*Ww)           // 16384
#define Kk 9
#define COUT 64
#define CK (Cc*Kk)           // 576
#define OFFCH 18
#define MASKCH 9
#define OMPAD 32             // 27 offset/mask channels padded to 32

// Scratch (device globals -- allocation-free per harness rules)
__device__ float g_off [Nn*OFFCH*HW];          // offsets [n][18][pq]
__device__ float g_mask[Nn*MASKCH*HW];         // sigmoid(mask) [n][9][pq]
__device__ unsigned short g_whi[Kk*COUT*Cc];   // w_dcn k-major bf16 hi [k][o][c]
__device__ unsigned short g_wlo[Kk*COUT*Cc];
__device__ unsigned short g_omhi[Kk*OMPAD*Cc]; // w_om k-major bf16 hi [k][o:32][c]
__device__ unsigned short g_omlo[Kk*OMPAD*Cc];

// ---------------------------------------------------------------------------
// Warp-MMA helpers
// ---------------------------------------------------------------------------
__device__ __forceinline__ uint32_t smem_u32(const void* p) {
    uint32_t a;
    asm("{ .reg .u64 t; cvta.to.shared.u64 t, %1; cvt.u32.u64 %0, t; }"
        : "=r"(a) : "l"(p));
    return a;
}
__device__ __forceinline__ void ldsm_x4(uint32_t* r, uint32_t addr) {
    asm volatile("ldmatrix.sync.aligned.m8n8.x4.shared.b16 {%0,%1,%2,%3}, [%4];"
        : "=r"(r[0]), "=r"(r[1]), "=r"(r[2]), "=r"(r[3]) : "r"(addr));
}
__device__ __forceinline__ void mma_bf16(float* c, const uint32_t* a, const uint32_t* b) {
    asm volatile(
        "mma.sync.aligned.m16n8k16.row.col.f32.bf16.bf16.f32 "
        "{%0,%1,%2,%3}, {%4,%5,%6,%7}, {%8,%9}, {%0,%1,%2,%3};"
        : "+f"(c[0]), "+f"(c[1]), "+f"(c[2]), "+f"(c[3])
        : "r"(a[0]), "r"(a[1]), "r"(a[2]), "r"(a[3]), "r"(b[0]), "r"(b[1]));
}
__device__ __forceinline__ uint32_t pack_hi(float v0, float v1) {
    return (uint32_t)__bfloat16_as_ushort(__float2bfloat16(v0)) |
           ((uint32_t)__bfloat16_as_ushort(__float2bfloat16(v1)) << 16);
}
__device__ __forceinline__ uint32_t pack_lo(float v0, float v1) {
    const float h0 = __bfloat162float(__float2bfloat16(v0));
    const float h1 = __bfloat162float(__float2bfloat16(v1));
    return (uint32_t)__bfloat16_as_ushort(__float2bfloat16(v0 - h0)) |
           ((uint32_t)__bfloat16_as_ushort(__float2bfloat16(v1 - h1)) << 16);
}

// bilinear sampling descriptor (per pixel, per tap)
struct Desc { int i00, i01, i10, i11; float w00, w01, w10, w11; };

__device__ __forceinline__ Desc make_sdesc(int n, int j, int pq) {
    Desc d;
    const int p = pq >> 7;
    const int q = pq & (Ww - 1);
    const float offy = g_off[((size_t)n * OFFCH + 2 * j)     * HW + pq];
    const float offx = g_off[((size_t)n * OFFCH + 2 * j + 1) * HW + pq];
    const float msk  = g_mask[((size_t)n * MASKCH + j) * HW + pq];
    const float y  = (float)(p - 1 + j / 3) + offy;
    const float xs = (float)(q - 1 + j % 3) + offx;
    const float y0f = floorf(y), x0f = floorf(xs);
    const float wy1 = y - y0f,   wx1 = xs - x0f;
    const int   y0 = (int)y0f,   x0 = (int)x0f;
    const int   y1 = y0 + 1,     x1 = x0 + 1;
    d.w00 = (1.f - wy1) * (1.f - wx1) * msk;
    d.w01 = (1.f - wy1) * wx1 * msk;
    d.w10 = wy1 * (1.f - wx1) * msk;
    d.w11 = wy1 * wx1 * msk;
    if (!(((unsigned)y0 < (unsigned)Hh) & ((unsigned)x0 < (unsigned)Ww))) d.w00 = 0.f;
    if (!(((unsigned)y0 < (unsigned)Hh) & ((unsigned)x1 < (unsigned)Ww))) d.w01 = 0.f;
    if (!(((unsigned)y1 < (unsigned)Hh) & ((unsigned)x0 < (unsigned)Ww))) d.w10 = 0.f;
    if (!(((unsigned)y1 < (unsigned)Hh) & ((unsigned)x1 < (unsigned)Ww))) d.w11 = 0.f;
    const int y0c = min(max(y0, 0), Hh - 1);
    const int y1c = min(max(y1, 0), Hh - 1);
    const int x0c = min(max(x0, 0), Ww - 1);
    const int x1c = min(max(x1, 0), Ww - 1);
    d.i00 = y0c * Ww + x0c;  d.i01 = y0c * Ww + x1c;
    d.i10 = y1c * Ww + x0c;  d.i11 = y1c * Ww + x1c;
    return d;
}
__device__ __forceinline__ float samp(const Desc& d, const float* xc) {
    return d.w00 * __ldg(xc + d.i00) + d.w01 * __ldg(xc + d.i01)
         + d.w10 * __ldg(xc + d.i10) + d.w11 * __ldg(xc + d.i11);
}

#define PITCH 144

// ---------------------------------------------------------------------------
// Kernel W-prep: k-major bf16 hi/lo for w_dcn and w_om (o-padded to 32)
// ---------------------------------------------------------------------------
#define WPREP_DCN (Kk*COUT*Cc)
#define WPREP_TOT (WPREP_DCN + Kk*OMPAD*Cc)
__global__ __launch_bounds__(256) void wprep_kernel(
    const float* __restrict__ w_dcn, const float* __restrict__ w_om)
{
    const int e = blockIdx.x * 256 + threadIdx.x;
    if (e >= WPREP_TOT) return;
    if (e < WPREP_DCN) {
        const int k = e / (COUT * Cc);
        const int r = e - k * (COUT * Cc);
        const int o = r >> 6;
        const int c = r & 63;
        const float w = __ldg(w_dcn + (size_t)o * CK + c * Kk + k);
        const __nv_bfloat16 hi = __float2bfloat16(w);
        g_whi[e] = __bfloat16_as_ushort(hi);
        g_wlo[e] = __bfloat16_as_ushort(__float2bfloat16(w - __bfloat162float(hi)));
    } else {
        const int e2 = e - WPREP_DCN;
        const int k = e2 >> 11;
        const int r = e2 & 2047;
        const int o = r >> 6;
        const int c = r & 63;
        float w = 0.f;
        if (o < 27) w = __ldg(w_om + (size_t)o * CK + c * Kk + k);
        const __nv_bfloat16 hi = __float2bfloat16(w);
        g_omhi[e2] = __bfloat16_as_ushort(hi);
        g_omlo[e2] = __bfloat16_as_ushort(__float2bfloat16(w - __bfloat162float(hi)));
    }
}

// ---------------------------------------------------------------------------
// Kernel A (HMMA, direct-register A): offset/mask conv.
//   D[128px, 32o] = sum_k Xtap_k[128, 64] x Wom_k[32, 64]^T.
// ---------------------------------------------------------------------------
#define CPITCH 144
__global__ __launch_bounds__(256, 3) void convA_mma_kernel(
    const float* __restrict__ x,
    const float* __restrict__ b_om)
{
    __shared__ char csm[2 * 32 * CPITCH];     // 9216 B: W hi, W lo
#define CWHI 0
#define CWLO (32 * CPITCH)
    const uint32_t sbase = smem_u32(csm);
    const int n   = blockIdx.z;
    const int p   = blockIdx.x;               // image row
    const int tid = threadIdx.x;
    const int wid = tid >> 5;
    const int lid = tid & 31;
    const int gr  = lid >> 2;
    const int r0  = wid * 16 + gr;            // image column (pixel)
    const int r1  = r0 + 8;

    const float* xn = x + (size_t)n * Cc * HW;

    float acc[4][4];
#pragma unroll
    for (int t = 0; t < 4; t++)
#pragma unroll
        for (int i = 0; i < 4; i++) acc[t][i] = 0.f;

    const int b_oofs = ((lid >> 4) << 3) + (lid & 7);
    const int b_cg   = ((lid >> 3) & 1);

    for (int j = 0; j < 9; j++) {
        __syncthreads();
        // stage W chunk: 1024 u32 per buffer
        {
            const uint32_t* whp = (const uint32_t*)g_omhi + j * 1024;
            const uint32_t* wlp = (const uint32_t*)g_omlo + j * 1024;
#pragma unroll
            for (int i = 0; i < 4; i++) {
                const int e  = tid + i * 256;
                const int o  = e >> 5;
                const int cg = e & 31;
                const uint32_t off = o * CPITCH + cg * 4;
                *(uint32_t*)(csm + CWHI + off) = __ldg(whp + e);
                *(uint32_t*)(csm + CWLO + off) = __ldg(wlp + e);
            }
        }
        // shifted-window parameters for tap j
        const int y   = p + j / 3 - 1;
        const int xc0 = r0 + j % 3 - 1;
        const int xc1 = xc0 + 8;
        const bool ok0 = ((unsigned)y < (unsigned)Hh) & ((unsigned)xc0 < (unsigned)Ww);
        const bool ok1 = ((unsigned)y < (unsigned)Hh) & ((unsigned)xc1 < (unsigned)Ww);
        const int off0 = y * Ww + xc0;
        const int off1 = y * Ww + xc1;
        __syncthreads();

#pragma unroll
        for (int ks = 0; ks < 4; ks++) {
            const int cb = ks * 16 + 2 * (lid & 3);
            const float* bA = xn + (size_t)cb * HW;
            const float* bB = bA + 8 * HW;
            float v0 = ok0 ? __ldg(bA + off0)          : 0.f;
            float v1 = ok0 ? __ldg(bA + HW + off0)     : 0.f;
            float v2 = ok1 ? __ldg(bA + off1)          : 0.f;
            float v3 = ok1 ? __ldg(bA + HW + off1)     : 0.f;
            float v4 = ok0 ? __ldg(bB + off0)          : 0.f;
            float v5 = ok0 ? __ldg(bB + HW + off0)     : 0.f;
            float v6 = ok1 ? __ldg(bB + off1)          : 0.f;
            float v7 = ok1 ? __ldg(bB + HW + off1)     : 0.f;
            uint32_t ahi[4], alo[4];
            ahi[0] = pack_hi(v0, v1); alo[0] = pack_lo(v0, v1);
            ahi[1] = pack_hi(v2, v3); alo[1] = pack_lo(v2, v3);
            ahi[2] = pack_hi(v4, v5); alo[2] = pack_lo(v4, v5);
            ahi[3] = pack_hi(v6, v7); alo[3] = pack_lo(v6, v7);
#pragma unroll
            for (int nt = 0; nt < 2; nt++) {
                uint32_t bh[4], bl[4];
                const uint32_t boff = (nt * 16 + b_oofs) * CPITCH + (ks * 2 + b_cg) * 16;
                ldsm_x4(bh, sbase + CWHI + boff);
                ldsm_x4(bl, sbase + CWLO + boff);
                mma_bf16(acc[nt * 2],     ahi, bh);
                mma_bf16(acc[nt * 2 + 1], ahi, bh + 2);
                mma_bf16(acc[nt * 2],     ahi, bl);
                mma_bf16(acc[nt * 2 + 1], ahi, bl + 2);
                mma_bf16(acc[nt * 2],     alo, bh);
                mma_bf16(acc[nt * 2 + 1], alo, bh + 2);
            }
        }
    }

    // Epilogue: bias, sigmoid on mask ch, scatter to g_off/g_mask
    const int px = p * Ww + wid * 16 + gr;
    float* offp = g_off  + (size_t)n * OFFCH  * HW;
    float* mskp = g_mask + (size_t)n * MASKCH * HW;
#pragma unroll
    for (int t = 0; t < 4; t++) {
        const int o0 = t * 8 + 2 * (lid & 3);
#pragma unroll
        for (int i = 0; i < 4; i++) {
            const int o  = o0 + (i & 1);
            const int pq = px + (i >> 1) * 8;
            if (o >= 27) continue;
            const float v = acc[t][i] + __ldg(b_om + o);
            if (o < OFFCH) offp[(size_t)o * HW + pq] = v;
            else           mskp[(size_t)(o - OFFCH) * HW + pq] = 1.f / (1.f + expf(-v));
        }
    }
}

// ---------------------------------------------------------------------------
// Kernel BC (HMMA, direct-register A): fused deform-sample + GEMM.
//   D[128px, 64o] = sum_k S_k[128, 64] x Wdcn_k[64, 64]^T.
// ---------------------------------------------------------------------------
__global__ __launch_bounds__(256, 2) void fusedBC_mma_kernel(
    const float* __restrict__ x,
    float* __restrict__ out)
{
    __shared__ char bsm[2 * 64 * PITCH];      // 18432 B: W hi, W lo
#define BWHI 0
#define BWLO (64 * PITCH)
    const uint32_t sbase = smem_u32(bsm);
    const int n   = blockIdx.z;
    const int j0  = blockIdx.x * 128;         // one image row of pixels
    const int tid = threadIdx.x;
    const int wid = tid >> 5;
    const int lid = tid & 31;
    const int gr  = lid >> 2;
    const int r0  = wid * 16 + gr;

    const float* xn = x + (size_t)n * Cc * HW;

    float acc[8][4];
#pragma unroll
    for (int t = 0; t < 8; t++)
#pragma unroll
        for (int i = 0; i < 4; i++) acc[t][i] = 0.f;

    const int b_oofs = ((lid >> 4) << 3) + (lid & 7);
    const int b_cg   = ((lid >> 3) & 1);

    for (int j = 0; j < 9; j++) {
        __syncthreads();
        // stage W chunk: 2048 u32 per buffer
        {
            const uint32_t* whp = (const uint32_t*)g_whi + j * 2048;
            const uint32_t* wlp = (const uint32_t*)g_wlo + j * 2048;
#pragma unroll
            for (int i = 0; i < 8; i++) {
                const int e  = tid + i * 256;
                const int o  = e >> 5;
                const int cg = e & 31;
                const uint32_t off = o * PITCH + cg * 4;
                *(uint32_t*)(bsm + BWHI + off) = __ldg(whp + e);
                *(uint32_t*)(bsm + BWLO + off) = __ldg(wlp + e);
            }
        }
        // per-thread descriptors for its two fragment rows
        const Desc d0 = make_sdesc(n, j, j0 + r0);
        const Desc d1 = make_sdesc(n, j, j0 + r0 + 8);
        __syncthreads();

#pragma unroll
        for (int ks = 0; ks < 4; ks++) {
            const int cb = ks * 16 + 2 * (lid & 3);
            const float* bA = xn + (size_t)cb * HW;
            const float* bB = bA + 8 * HW;
            const float v0 = samp(d0, bA);
            const float v1 = samp(d0, bA + HW);
            const float v2 = samp(d1, bA);
            const float v3 = samp(d1, bA + HW);
            const float v4 = samp(d0, bB);
            const float v5 = samp(d0, bB + HW);
            const float v6 = samp(d1, bB);
            const float v7 = samp(d1, bB + HW);
            uint32_t ahi[4], alo[4];
            ahi[0] = pack_hi(v0, v1); alo[0] = pack_lo(v0, v1);
            ahi[1] = pack_hi(v2, v3); alo[1] = pack_lo(v2, v3);
            ahi[2] = pack_hi(v4, v5); alo[2] = pack_lo(v4, v5);
            ahi[3] = pack_hi(v6, v7); alo[3] = pack_lo(v6, v7);
#pragma unroll
            for (int nt = 0; nt < 4; nt++) {
                uint32_t bh[4], bl[4];
                const uint32_t boff = (nt * 16 + b_oofs) * PITCH + (ks * 2 + b_cg) * 16;
                ldsm_x4(bh, sbase + BWHI + boff);
                ldsm_x4(bl, sbase + BWLO + boff);
                mma_bf16(acc[nt * 2],     ahi, bh);
                mma_bf16(acc[nt * 2 + 1], ahi, bh + 2);
                mma_bf16(acc[nt * 2],     ahi, bl);
                mma_bf16(acc[nt * 2 + 1], ahi, bl + 2);
                mma_bf16(acc[nt * 2],     alo, bh);
                mma_bf16(acc[nt * 2 + 1], alo, bh + 2);
            }
        }
    }

    // Epilogue: D fragment -> out[n][o][pq]
    const int px = j0 + wid * 16 + gr;
    float* op = out + (size_t)n * COUT * HW;
#pragma unroll
    for (int t = 0; t < 8; t++) {
        const int o0 = t * 8 + 2 * (lid & 3);
        op[(size_t)o0       * HW + px    ] = acc[t][0];
        op[(size_t)(o0 + 1) * HW + px    ] = acc[t][1];
        op[(size_t)o0       * HW + px + 8] = acc[t][2];
        op[(size_t)(o0 + 1) * HW + px + 8] = acc[t][3];
    }
}

// ---------------------------------------------------------------------------
extern "C" void kernel_launch(void* const* d_in, const int* in_sizes, int n_in,
                              void* d_out, int out_size)
{
    const float* x     = (const float*)d_in[0];  // (4,64,128,128)
    const float* w_om  = (const float*)d_in[1];  // (27,64,3,3)
    const float* b_om  = (const float*)d_in[2];  // (27,)
    const float* w_dcn = (const float*)d_in[3];  // (64,64,3,3)
    float* out = (float*)d_out;                  // (4,64,128,128)

    wprep_kernel<<<(WPREP_TOT + 255) / 256, 256>>>(w_dcn, w_om);

    dim3 gA(Hh, 1, Nn);                          // 512 blocks
    convA_mma_kernel<<<gA, 256>>>(x, b_om);

    dim3 gBC(HW / 128, 1, Nn);                   // 512 blocks
    fusedBC_mma_kernel<<<gBC, 256>>>(x, out);
}

// round 9
// speedup vs baseline: 1.4709x; 1.4709x over previous
#include <cuda_runtime.h>
#include <cuda_bf16.h>
#include <math.h>
#include <cstdint>

// Problem constants
#define Nn 4
#define Cc 64
#define Hh 128
#define Ww 128
#define HW (Hh*Ww)           // 16384
#define Kk 9
#define COUT 64
#define CK (Cc*Kk)           // 576
#define OFFCH 18
#define MASKCH 9
#define OMPAD 32

// Scratch (device globals -- allocation-free per harness rules)
__device__ float g_off [Nn*OFFCH*HW];
__device__ float g_mask[Nn*MASKCH*HW];
__device__ unsigned short g_whi[Kk*COUT*Cc];   // w_dcn k-major bf16 hi [k][o][c]
__device__ unsigned short g_wlo[Kk*COUT*Cc];
__device__ unsigned short g_omhi[Kk*OMPAD*Cc];
__device__ unsigned short g_omlo[Kk*OMPAD*Cc];

// ---------------------------------------------------------------------------
// Warp-MMA helpers
// ---------------------------------------------------------------------------
__device__ __forceinline__ uint32_t smem_u32(const void* p) {
    uint32_t a;
    asm("{ .reg .u64 t; cvta.to.shared.u64 t, %1; cvt.u32.u64 %0, t; }"
        : "=r"(a) : "l"(p));
    return a;
}
__device__ __forceinline__ void ldsm_x4(uint32_t* r, uint32_t addr) {
    asm volatile("ldmatrix.sync.aligned.m8n8.x4.shared.b16 {%0,%1,%2,%3}, [%4];"
        : "=r"(r[0]), "=r"(r[1]), "=r"(r[2]), "=r"(r[3]) : "r"(addr));
}
__device__ __forceinline__ void ldsm_x4_t(uint32_t* r, uint32_t addr) {
    asm volatile("ldmatrix.sync.aligned.m8n8.x4.trans.shared.b16 {%0,%1,%2,%3}, [%4];"
        : "=r"(r[0]), "=r"(r[1]), "=r"(r[2]), "=r"(r[3]) : "r"(addr));
}
__device__ __forceinline__ void mma_bf16(float* c, const uint32_t* a, const uint32_t* b) {
    asm volatile(
        "mma.sync.aligned.m16n8k16.row.col.f32.bf16.bf16.f32 "
        "{%0,%1,%2,%3}, {%4,%5,%6,%7}, {%8,%9}, {%0,%1,%2,%3};"
        : "+f"(c[0]), "+f"(c[1]), "+f"(c[2]), "+f"(c[3])
        : "r"(a[0]), "r"(a[1]), "r"(a[2]), "r"(a[3]), "r"(b[0]), "r"(b[1]));
}
__device__ __forceinline__ uint32_t pack_hi(float v0, float v1) {
    return (uint32_t)__bfloat16_as_ushort(__float2bfloat16(v0)) |
           ((uint32_t)__bfloat16_as_ushort(__float2bfloat16(v1)) << 16);
}
__device__ __forceinline__ uint32_t pack_lo(float v0, float v1) {
    const float h0 = __bfloat162float(__float2bfloat16(v0));
    const float h1 = __bfloat162float(__float2bfloat16(v1));
    return (uint32_t)__bfloat16_as_ushort(__float2bfloat16(v0 - h0)) |
           ((uint32_t)__bfloat16_as_ushort(__float2bfloat16(v1 - h1)) << 16);
}
__device__ __forceinline__ void split_pack(float v0, float v1,
                                           uint32_t& hi2, uint32_t& lo2) {
    hi2 = pack_hi(v0, v1);
    lo2 = pack_lo(v0, v1);
}

// bilinear sampling descriptor (per pixel, per tap)
struct Desc { int i00, i01, i10, i11; float w00, w01, w10, w11; };

__device__ __forceinline__ Desc make_sdesc(int n, int j, int pq) {
    Desc d;
    const int p = pq >> 7;
    const int q = pq & (Ww - 1);
    const float offy = g_off[((size_t)n * OFFCH + 2 * j)     * HW + pq];
    const float offx = g_off[((size_t)n * OFFCH + 2 * j + 1) * HW + pq];
    const float msk  = g_mask[((size_t)n * MASKCH + j) * HW + pq];
    const float y  = (float)(p - 1 + j / 3) + offy;
    const float xs = (float)(q - 1 + j % 3) + offx;
    const float y0f = floorf(y), x0f = floorf(xs);
    const float wy1 = y - y0f,   wx1 = xs - x0f;
    const int   y0 = (int)y0f,   x0 = (int)x0f;
    const int   y1 = y0 + 1,     x1 = x0 + 1;
    d.w00 = (1.f - wy1) * (1.f - wx1) * msk;
    d.w01 = (1.f - wy1) * wx1 * msk;
    d.w10 = wy1 * (1.f - wx1) * msk;
    d.w11 = wy1 * wx1 * msk;
    if (!(((unsigned)y0 < (unsigned)Hh) & ((unsigned)x0 < (unsigned)Ww))) d.w00 = 0.f;
    if (!(((unsigned)y0 < (unsigned)Hh) & ((unsigned)x1 < (unsigned)Ww))) d.w01 = 0.f;
    if (!(((unsigned)y1 < (unsigned)Hh) & ((unsigned)x0 < (unsigned)Ww))) d.w10 = 0.f;
    if (!(((unsigned)y1 < (unsigned)Hh) & ((unsigned)x1 < (unsigned)Ww))) d.w11 = 0.f;
    const int y0c = min(max(y0, 0), Hh - 1);
    const int y1c = min(max(y1, 0), Hh - 1);
    const int x0c = min(max(x0, 0), Ww - 1);
    const int x1c = min(max(x1, 0), Ww - 1);
    d.i00 = y0c * Ww + x0c;  d.i01 = y0c * Ww + x1c;
    d.i10 = y1c * Ww + x0c;  d.i11 = y1c * Ww + x1c;
    return d;
}
__device__ __forceinline__ float samp(const Desc& d, const float* xc) {
    return d.w00 * __ldg(xc + d.i00) + d.w01 * __ldg(xc + d.i01)
         + d.w10 * __ldg(xc + d.i10) + d.w11 * __ldg(xc + d.i11);
}

#define PITCH  144     // W rows: 128B + 16B skew
#define TPITCH 272     // S^T rows: 256B + 16B skew (17*16 -> conflict-free LDSM)

// Dynamic SMEM layout for fusedBC
#define T_SHI 0                       // 64*272 = 17408
#define T_SLO (T_SHI + 64*TPITCH)
#define T_WHI (T_SLO + 64*TPITCH)     // 64*144 = 9216
#define T_WLO (T_WHI + 64*PITCH)
#define T_TOTAL (T_WLO + 64*PITCH)    // 53248

// ---------------------------------------------------------------------------
// Kernel W-prep (unchanged)
// ---------------------------------------------------------------------------
#define WPREP_DCN (Kk*COUT*Cc)
#define WPREP_TOT (WPREP_DCN + Kk*OMPAD*Cc)
__global__ __launch_bounds__(256) void wprep_kernel(
    const float* __restrict__ w_dcn, const float* __restrict__ w_om)
{
    const int e = blockIdx.x * 256 + threadIdx.x;
    if (e >= WPREP_TOT) return;
    if (e < WPREP_DCN) {
        const int k = e / (COUT * Cc);
        const int r = e - k * (COUT * Cc);
        const int o = r >> 6;
        const int c = r & 63;
        const float w = __ldg(w_dcn + (size_t)o * CK + c * Kk + k);
        const __nv_bfloat16 hi = __float2bfloat16(w);
        g_whi[e] = __bfloat16_as_ushort(hi);
        g_wlo[e] = __bfloat16_as_ushort(__float2bfloat16(w - __bfloat162float(hi)));
    } else {
        const int e2 = e - WPREP_DCN;
        const int k = e2 >> 11;
        const int r = e2 & 2047;
        const int o = r >> 6;
        const int c = r & 63;
        float w = 0.f;
        if (o < 27) w = __ldg(w_om + (size_t)o * CK + c * Kk + k);
        const __nv_bfloat16 hi = __float2bfloat16(w);
        g_omhi[e2] = __bfloat16_as_ushort(hi);
        g_omlo[e2] = __bfloat16_as_ushort(__float2bfloat16(w - __bfloat162float(hi)));
    }
}

// ---------------------------------------------------------------------------
// Kernel A (HMMA): offset/mask conv. (round-7 version, measured ~36us)
// ---------------------------------------------------------------------------
#define CPITCH 144
__global__ __launch_bounds__(256, 3) void convA_mma_kernel(
    const float* __restrict__ x,
    const float* __restrict__ b_om)
{
    __shared__ char csm[128 * CPITCH * 2 + 32 * CPITCH * 2];  // 46080 B
#define CSHI 0
#define CSLO (128 * CPITCH)
#define CWHI (2 * 128 * CPITCH)
#define CWLO (2 * 128 * CPITCH + 32 * CPITCH)
    const uint32_t sbase = smem_u32(csm);
    const int n   = blockIdx.z;
    const int p   = blockIdx.x;
    const int tid = threadIdx.x;
    const int wid = tid >> 5;
    const int lid = tid & 31;

    const float* xn = x + (size_t)n * Cc * HW;

    float acc[4][4];
#pragma unroll
    for (int t = 0; t < 4; t++)
#pragma unroll
        for (int i = 0; i < 4; i++) acc[t][i] = 0.f;

    const int a_row  = wid * 16 + (((lid >> 3) & 1) << 3) + (lid & 7);
    const int a_cg   = (lid >> 4);
    const int b_oofs = ((lid >> 4) << 3) + (lid & 7);
    const int b_cg   = ((lid >> 3) & 1);

    const int g_row  = tid & 127;
    const int g_half = tid >> 7;

    for (int j = 0; j < 9; j++) {
        __syncthreads();
        {
            const uint32_t* whp = (const uint32_t*)g_omhi + j * 1024;
            const uint32_t* wlp = (const uint32_t*)g_omlo + j * 1024;
#pragma unroll
            for (int i = 0; i < 4; i++) {
                const int e  = tid + i * 256;
                const int o  = e >> 5;
                const int cg = e & 31;
                const uint32_t off = o * CPITCH + cg * 4;
                *(uint32_t*)(csm + CWHI + off) = __ldg(whp + e);
                *(uint32_t*)(csm + CWLO + off) = __ldg(wlp + e);
            }
        }
        {
            const int y  = p + j / 3 - 1;
            const int xc = g_row + j % 3 - 1;
            const bool ok = ((unsigned)y < (unsigned)Hh) & ((unsigned)xc < (unsigned)Ww);
            const float* bp = xn + (size_t)g_half * 32 * HW + y * Ww + xc;
            uint32_t soff = g_row * CPITCH + (g_half * 16) * 4;
#pragma unroll
            for (int i = 0; i < 16; i++) {
                const float v0 = ok ? __ldg(bp)      : 0.f;
                const float v1 = ok ? __ldg(bp + HW) : 0.f;
                bp += 2 * HW;
                uint32_t hi2, lo2;
                split_pack(v0, v1, hi2, lo2);
                *(uint32_t*)(csm + CSHI + soff) = hi2;
                *(uint32_t*)(csm + CSLO + soff) = lo2;
                soff += 4;
            }
        }
        __syncthreads();

#pragma unroll
        for (int ks = 0; ks < 4; ks++) {
            uint32_t ahi[4], alo[4];
            const uint32_t aoff = a_row * CPITCH + (ks * 2 + a_cg) * 16;
            ldsm_x4(ahi, sbase + CSHI + aoff);
            ldsm_x4(alo, sbase + CSLO + aoff);
#pragma unroll
            for (int nt = 0; nt < 2; nt++) {
                uint32_t bh[4], bl[4];
                const uint32_t boff = (nt * 16 + b_oofs) * CPITCH + (ks * 2 + b_cg) * 16;
                ldsm_x4(bh, sbase + CWHI + boff);
                ldsm_x4(bl, sbase + CWLO + boff);
                mma_bf16(acc[nt * 2],     ahi, bh);
                mma_bf16(acc[nt * 2 + 1], ahi, bh + 2);
                mma_bf16(acc[nt * 2],     ahi, bl);
                mma_bf16(acc[nt * 2 + 1], ahi, bl + 2);
                mma_bf16(acc[nt * 2],     alo, bh);
                mma_bf16(acc[nt * 2 + 1], alo, bh + 2);
            }
        }
    }

    const int px = p * Ww + wid * 16 + (lid >> 2);
    float* offp = g_off  + (size_t)n * OFFCH  * HW;
    float* mskp = g_mask + (size_t)n * MASKCH * HW;
#pragma unroll
    for (int t = 0; t < 4; t++) {
        const int o0 = t * 8 + 2 * (lid & 3);
#pragma unroll
        for (int i = 0; i < 4; i++) {
            const int o  = o0 + (i & 1);
            const int pq = px + (i >> 1) * 8;
            if (o >= 27) continue;
            const float v = acc[t][i] + __ldg(b_om + o);
            if (o < OFFCH) offp[(size_t)o * HW + pq] = v;
            else           mskp[(size_t)(o - OFFCH) * HW + pq] = 1.f / (1.f + expf(-v));
        }
    }
}

// ---------------------------------------------------------------------------
// Kernel BC: fused deform-sample + HMMA GEMM with TRANSPOSED S staging.
//   S^T[ck][px] in SMEM; gather = warp-uniform channel, 64 consecutive px;
//   conflict-free STS; A-fragment via ldmatrix.x4.trans.
// ---------------------------------------------------------------------------
__global__ __launch_bounds__(256, 2) void fusedBC_mma_kernel(
    const float* __restrict__ x,
    float* __restrict__ out)
{
    extern __shared__ char smem[];
    const uint32_t sbase = smem_u32(smem);
    const int n   = blockIdx.z;
    const int j0  = blockIdx.x * 128;
    const int tid = threadIdx.x;
    const int wid = tid >> 5;
    const int lid = tid & 31;

    const float* xn = x + (size_t)n * Cc * HW;

    float acc[8][4];
#pragma unroll
    for (int t = 0; t < 8; t++)
#pragma unroll
        for (int i = 0; i < 4; i++) acc[t][i] = 0.f;

    // A-frag ldsm.trans address components: slot = lid>>3, r = lid&7
    //   ck = ks*16 + r + 8*(slot>>1), px = wid*16 + 8*(slot&1)
    const int a_ckb = (lid & 7) + (((lid >> 3) & 2) << 2);
    const int a_px  = wid * 16 + (((lid >> 3) & 1) << 3);
    // B-frag (normal ldsm) components, unchanged
    const int b_oofs = ((lid >> 4) << 3) + (lid & 7);
    const int b_cg   = ((lid >> 3) & 1);

    // gather mapping: pixel pair + channel quarter
    const int pp  = tid & 63;        // pixels 2pp, 2pp+1
    const int ckq = tid >> 6;        // 0..3 -> channels ckq*16..+15

    for (int j = 0; j < 9; j++) {
        __syncthreads();
        // stage W chunk: 2048 u32 per buffer
        {
            const uint32_t* whp = (const uint32_t*)g_whi + j * 2048;
            const uint32_t* wlp = (const uint32_t*)g_wlo + j * 2048;
#pragma unroll
            for (int i = 0; i < 8; i++) {
                const int e  = tid + i * 256;
                const int o  = e >> 5;
                const int cg = e & 31;
                const uint32_t off = o * PITCH + cg * 4;
                *(uint32_t*)(smem + T_WHI + off) = __ldg(whp + e);
                *(uint32_t*)(smem + T_WLO + off) = __ldg(wlp + e);
            }
        }
        // private descriptors for this thread's two pixels (hoisted over c)
        const Desc d0 = make_sdesc(n, j, j0 + 2 * pp);
        const Desc d1 = make_sdesc(n, j, j0 + 2 * pp + 1);
        // gather 16 channels x 2 pixels into S^T
        {
            const float* xc = xn + (size_t)(ckq * 16) * HW;
            uint32_t soff = (ckq * 16) * TPITCH + pp * 4;
#pragma unroll
            for (int i = 0; i < 16; i++) {
                const float v0 = samp(d0, xc);
                const float v1 = samp(d1, xc);
                xc += HW;
                *(uint32_t*)(smem + T_SHI + soff) = pack_hi(v0, v1);
                *(uint32_t*)(smem + T_SLO + soff) = pack_lo(v0, v1);
                soff += TPITCH;
            }
        }
        __syncthreads();

#pragma unroll
        for (int ks = 0; ks < 4; ks++) {
            uint32_t ahi[4], alo[4];
            const uint32_t aoff = (ks * 16 + a_ckb) * TPITCH + a_px * 2;
            ldsm_x4_t(ahi, sbase + T_SHI + aoff);
            ldsm_x4_t(alo, sbase + T_SLO + aoff);
#pragma unroll
            for (int nt = 0; nt < 4; nt++) {
                uint32_t bh[4], bl[4];
                const uint32_t boff = (nt * 16 + b_oofs) * PITCH + (ks * 2 + b_cg) * 16;
                ldsm_x4(bh, sbase + T_WHI + boff);
                ldsm_x4(bl, sbase + T_WLO + boff);
                mma_bf16(acc[nt * 2],     ahi, bh);
                mma_bf16(acc[nt * 2 + 1], ahi, bh + 2);
                mma_bf16(acc[nt * 2],     ahi, bl);
                mma_bf16(acc[nt * 2 + 1], ahi, bl + 2);
                mma_bf16(acc[nt * 2],     alo, bh);
                mma_bf16(acc[nt * 2 + 1], alo, bh + 2);
            }
        }
    }

    // Epilogue: D fragment -> out[n][o][pq]
    const int px = j0 + wid * 16 + (lid >> 2);
    float* op = out + (size_t)n * COUT * HW;
#pragma unroll
    for (int t = 0; t < 8; t++) {
        const int o0 = t * 8 + 2 * (lid & 3);
        op[(size_t)o0       * HW + px    ] = acc[t][0];
        op[(size_t)(o0 + 1) * HW + px    ] = acc[t][1];
        op[(size_t)o0       * HW + px + 8] = acc[t][2];
        op[(size_t)(o0 + 1) * HW + px + 8] = acc[t][3];
    }
}

// ---------------------------------------------------------------------------
extern "C" void kernel_launch(void* const* d_in, const int* in_sizes, int n_in,
                              void* d_out, int out_size)
{
    const float* x     = (const float*)d_in[0];  // (4,64,128,128)
    const float* w_om  = (const float*)d_in[1];  // (27,64,3,3)
    const float* b_om  = (const float*)d_in[2];  // (27,)
    const float* w_dcn = (const float*)d_in[3];  // (64,64,3,3)
    float* out = (float*)d_out;                  // (4,64,128,128)

    wprep_kernel<<<(WPREP_TOT + 255) / 256, 256>>>(w_dcn, w_om);

    dim3 gA(Hh, 1, Nn);                          // 512 blocks
    convA_mma_kernel<<<gA, 256>>>(x, b_om);

    cudaFuncSetAttribute(fusedBC_mma_kernel,
                         cudaFuncAttributeMaxDynamicSharedMemorySize, T_TOTAL);
    dim3 gBC(HW / 128, 1, Nn);                   // 512 blocks
    fusedBC_mma_kernel<<<gBC, 256, T_TOTAL>>>(x, out);
}

// round 10
// speedup vs baseline: 1.5479x; 1.0524x over previous
#include <cuda_runtime.h>
#include <cuda_bf16.h>
#include <math.h>
#include <cstdint>

// Problem constants
#define Nn 4
#define Cc 64
#define Hh 128
#define Ww 128
#define HW (Hh*Ww)           // 16384
#define Kk 9
#define COUT 64
#define CK (Cc*Kk)           // 576
#define OFFCH 18
#define MASKCH 9
#define OMPAD 32

// Scratch (device globals -- allocation-free per harness rules)
__device__ float g_off [Nn*OFFCH*HW];
__device__ float g_mask[Nn*MASKCH*HW];
__device__ unsigned short g_whi[Kk*COUT*Cc];   // w_dcn k-major bf16 hi [k][o][c]
__device__ unsigned short g_wlo[Kk*COUT*Cc];
__device__ unsigned short g_omhi[Kk*OMPAD*Cc];
__device__ unsigned short g_omlo[Kk*OMPAD*Cc];

// ---------------------------------------------------------------------------
// Warp-MMA helpers
// ---------------------------------------------------------------------------
__device__ __forceinline__ uint32_t smem_u32(const void* p) {
    uint32_t a;
    asm("{ .reg .u64 t; cvta.to.shared.u64 t, %1; cvt.u32.u64 %0, t; }"
        : "=r"(a) : "l"(p));
    return a;
}
__device__ __forceinline__ void ldsm_x4(uint32_t* r, uint32_t addr) {
    asm volatile("ldmatrix.sync.aligned.m8n8.x4.shared.b16 {%0,%1,%2,%3}, [%4];"
        : "=r"(r[0]), "=r"(r[1]), "=r"(r[2]), "=r"(r[3]) : "r"(addr));
}
__device__ __forceinline__ void ldsm_x4_t(uint32_t* r, uint32_t addr) {
    asm volatile("ldmatrix.sync.aligned.m8n8.x4.trans.shared.b16 {%0,%1,%2,%3}, [%4];"
        : "=r"(r[0]), "=r"(r[1]), "=r"(r[2]), "=r"(r[3]) : "r"(addr));
}
__device__ __forceinline__ void mma_bf16(float* c, const uint32_t* a, const uint32_t* b) {
    asm volatile(
        "mma.sync.aligned.m16n8k16.row.col.f32.bf16.bf16.f32 "
        "{%0,%1,%2,%3}, {%4,%5,%6,%7}, {%8,%9}, {%0,%1,%2,%3};"
        : "+f"(c[0]), "+f"(c[1]), "+f"(c[2]), "+f"(c[3])
        : "r"(a[0]), "r"(a[1]), "r"(a[2]), "r"(a[3]), "r"(b[0]), "r"(b[1]));
}
// fast 2-way bf16 split: hi = RN(v), lo = RN(v - float(hi)); one cvt.bf16x2 each
__device__ __forceinline__ void split_pack(float v0, float v1,
                                           uint32_t& hi2, uint32_t& lo2) {
    asm("cvt.rn.bf16x2.f32 %0, %2, %1;" : "=r"(hi2) : "f"(v0), "f"(v1));
    const float h0 = __uint_as_float(hi2 << 16);
    const float h1 = __uint_as_float(hi2 & 0xFFFF0000u);
    const float l0 = v0 - h0;
    const float l1 = v1 - h1;
    asm("cvt.rn.bf16x2.f32 %0, %2, %1;" : "=r"(lo2) : "f"(l0), "f"(l1));
}

// bilinear sampling descriptor (per pixel, per tap)
struct Desc { int i00, i01, i10, i11; float w00, w01, w10, w11; };

__device__ __forceinline__ Desc make_sdesc(int n, int j, int pq) {
    Desc d;
    const int p = pq >> 7;
    const int q = pq & (Ww - 1);
    const float offy = g_off[((size_t)n * OFFCH + 2 * j)     * HW + pq];
    const float offx = g_off[((size_t)n * OFFCH + 2 * j + 1) * HW + pq];
    const float msk  = g_mask[((size_t)n * MASKCH + j) * HW + pq];
    const float y  = (float)(p - 1 + j / 3) + offy;
    const float xs = (float)(q - 1 + j % 3) + offx;
    const float y0f = floorf(y), x0f = floorf(xs);
    const float wy1 = y - y0f,   wx1 = xs - x0f;
    const int   y0 = (int)y0f,   x0 = (int)x0f;
    const int   y1 = y0 + 1,     x1 = x0 + 1;
    d.w00 = (1.f - wy1) * (1.f - wx1) * msk;
    d.w01 = (1.f - wy1) * wx1 * msk;
    d.w10 = wy1 * (1.f - wx1) * msk;
    d.w11 = wy1 * wx1 * msk;
    if (!(((unsigned)y0 < (unsigned)Hh) & ((unsigned)x0 < (unsigned)Ww))) d.w00 = 0.f;
    if (!(((unsigned)y0 < (unsigned)Hh) & ((unsigned)x1 < (unsigned)Ww))) d.w01 = 0.f;
    if (!(((unsigned)y1 < (unsigned)Hh) & ((unsigned)x0 < (unsigned)Ww))) d.w10 = 0.f;
    if (!(((unsigned)y1 < (unsigned)Hh) & ((unsigned)x1 < (unsigned)Ww))) d.w11 = 0.f;
    const int y0c = min(max(y0, 0), Hh - 1);
    const int y1c = min(max(y1, 0), Hh - 1);
    const int x0c = min(max(x0, 0), Ww - 1);
    const int x1c = min(max(x1, 0), Ww - 1);
    d.i00 = y0c * Ww + x0c;  d.i01 = y0c * Ww + x1c;
    d.i10 = y1c * Ww + x0c;  d.i11 = y1c * Ww + x1c;
    return d;
}
__device__ __forceinline__ float samp(const Desc& d, const float* xc) {
    return d.w00 * __ldg(xc + d.i00) + d.w01 * __ldg(xc + d.i01)
         + d.w10 * __ldg(xc + d.i10) + d.w11 * __ldg(xc + d.i11);
}

#define PITCH   144    // W rows: 128B + 16B skew
#define TPITCH2 528    // S^T rows (256 px): 512B + 16B skew (33*16 -> clean LDSM)

// Dynamic SMEM layout for fusedBC (256-px tile)
#define T_SHI 0                        // 64*528 = 33792
#define T_SLO (T_SHI + 64*TPITCH2)
#define T_WHI (T_SLO + 64*TPITCH2)     // 64*144 = 9216
#define T_WLO (T_WHI + 64*PITCH)
#define T_TOTAL (T_WLO + 64*PITCH)     // 86016 B -> 2 CTAs/SM

// ---------------------------------------------------------------------------
// Kernel W-prep (unchanged)
// ---------------------------------------------------------------------------
#define WPREP_DCN (Kk*COUT*Cc)
#define WPREP_TOT (WPREP_DCN + Kk*OMPAD*Cc)
__global__ __launch_bounds__(256) void wprep_kernel(
    const float* __restrict__ w_dcn, const float* __restrict__ w_om)
{
    const int e = blockIdx.x * 256 + threadIdx.x;
    if (e >= WPREP_TOT) return;
    if (e < WPREP_DCN) {
        const int k = e / (COUT * Cc);
        const int r = e - k * (COUT * Cc);
        const int o = r >> 6;
        const int c = r & 63;
        const float w = __ldg(w_dcn + (size_t)o * CK + c * Kk + k);
        const __nv_bfloat16 hi = __float2bfloat16(w);
        g_whi[e] = __bfloat16_as_ushort(hi);
        g_wlo[e] = __bfloat16_as_ushort(__float2bfloat16(w - __bfloat162float(hi)));
    } else {
        const int e2 = e - WPREP_DCN;
        const int k = e2 >> 11;
        const int r = e2 & 2047;
        const int o = r >> 6;
        const int c = r & 63;
        float w = 0.f;
        if (o < 27) w = __ldg(w_om + (size_t)o * CK + c * Kk + k);
        const __nv_bfloat16 hi = __float2bfloat16(w);
        g_omhi[e2] = __bfloat16_as_ushort(hi);
        g_omlo[e2] = __bfloat16_as_ushort(__float2bfloat16(w - __bfloat162float(hi)));
    }
}

// ---------------------------------------------------------------------------
// Kernel A (HMMA): offset/mask conv. (round-7/9 version, ~36us)
// ---------------------------------------------------------------------------
#define CPITCH 144
__global__ __launch_bounds__(256, 3) void convA_mma_kernel(
    const float* __restrict__ x,
    const float* __restrict__ b_om)
{
    __shared__ char csm[128 * CPITCH * 2 + 32 * CPITCH * 2];  // 46080 B
#define CSHI 0
#define CSLO (128 * CPITCH)
#define CWHI (2 * 128 * CPITCH)
#define CWLO (2 * 128 * CPITCH + 32 * CPITCH)
    const uint32_t sbase = smem_u32(csm);
    const int n   = blockIdx.z;
    const int p   = blockIdx.x;
    const int tid = threadIdx.x;
    const int wid = tid >> 5;
    const int lid = tid & 31;

    const float* xn = x + (size_t)n * Cc * HW;

    float acc[4][4];
#pragma unroll
    for (int t = 0; t < 4; t++)
#pragma unroll
        for (int i = 0; i < 4; i++) acc[t][i] = 0.f;

    const int a_row  = wid * 16 + (((lid >> 3) & 1) << 3) + (lid & 7);
    const int a_cg   = (lid >> 4);
    const int b_oofs = ((lid >> 4) << 3) + (lid & 7);
    const int b_cg   = ((lid >> 3) & 1);

    const int g_row  = tid & 127;
    const int g_half = tid >> 7;

    for (int j = 0; j < 9; j++) {
        __syncthreads();
        {
            const uint32_t* whp = (const uint32_t*)g_omhi + j * 1024;
            const uint32_t* wlp = (const uint32_t*)g_omlo + j * 1024;
#pragma unroll
            for (int i = 0; i < 4; i++) {
                const int e  = tid + i * 256;
                const int o  = e >> 5;
                const int cg = e & 31;
                const uint32_t off = o * CPITCH + cg * 4;
                *(uint32_t*)(csm + CWHI + off) = __ldg(whp + e);
                *(uint32_t*)(csm + CWLO + off) = __ldg(wlp + e);
            }
        }
        {
            const int y  = p + j / 3 - 1;
            const int xc = g_row + j % 3 - 1;
            const bool ok = ((unsigned)y < (unsigned)Hh) & ((unsigned)xc < (unsigned)Ww);
            const float* bp = xn + (size_t)g_half * 32 * HW + y * Ww + xc;
            uint32_t soff = g_row * CPITCH + (g_half * 16) * 4;
#pragma unroll
            for (int i = 0; i < 16; i++) {
                const float v0 = ok ? __ldg(bp)      : 0.f;
                const float v1 = ok ? __ldg(bp + HW) : 0.f;
                bp += 2 * HW;
                uint32_t hi2, lo2;
                split_pack(v0, v1, hi2, lo2);
                *(uint32_t*)(csm + CSHI + soff) = hi2;
                *(uint32_t*)(csm + CSLO + soff) = lo2;
                soff += 4;
            }
        }
        __syncthreads();

#pragma unroll
        for (int ks = 0; ks < 4; ks++) {
            uint32_t ahi[4], alo[4];
            const uint32_t aoff = a_row * CPITCH + (ks * 2 + a_cg) * 16;
            ldsm_x4(ahi, sbase + CSHI + aoff);
            ldsm_x4(alo, sbase + CSLO + aoff);
#pragma unroll
            for (int nt = 0; nt < 2; nt++) {
                uint32_t bh[4], bl[4];
                const uint32_t boff = (nt * 16 + b_oofs) * CPITCH + (ks * 2 + b_cg) * 16;
                ldsm_x4(bh, sbase + CWHI + boff);
                ldsm_x4(bl, sbase + CWLO + boff);
                mma_bf16(acc[nt * 2],     ahi, bh);
                mma_bf16(acc[nt * 2 + 1], ahi, bh + 2);
                mma_bf16(acc[nt * 2],     ahi, bl);
                mma_bf16(acc[nt * 2 + 1], ahi, bl + 2);
                mma_bf16(acc[nt * 2],     alo, bh);
                mma_bf16(acc[nt * 2 + 1], alo, bh + 2);
            }
        }
    }

    const int px = p * Ww + wid * 16 + (lid >> 2);
    float* offp = g_off  + (size_t)n * OFFCH  * HW;
    float* mskp = g_mask + (size_t)n * MASKCH * HW;
#pragma unroll
    for (int t = 0; t < 4; t++) {
        const int o0 = t * 8 + 2 * (lid & 3);
#pragma unroll
        for (int i = 0; i < 4; i++) {
            const int o  = o0 + (i & 1);
            const int pq = px + (i >> 1) * 8;
            if (o >= 27) continue;
            const float v = acc[t][i] + __ldg(b_om + o);
            if (o < OFFCH) offp[(size_t)o * HW + pq] = v;
            else           mskp[(size_t)(o - OFFCH) * HW + pq] = 1.f / (1.f + expf(-v));
        }
    }
}

// ---------------------------------------------------------------------------
// Kernel BC: fused deform-sample + HMMA GEMM, 256-px M-tile, S^T staging.
// ---------------------------------------------------------------------------
__global__ __launch_bounds__(256, 2) void fusedBC_mma_kernel(
    const float* __restrict__ x,
    float* __restrict__ out)
{
    extern __shared__ char smem[];
    const uint32_t sbase = smem_u32(smem);
    const int n   = blockIdx.z;
    const int j0  = blockIdx.x * 256;      // two image rows of pixels
    const int tid = threadIdx.x;
    const int wid = tid >> 5;
    const int lid = tid & 31;

    const float* xn = x + (size_t)n * Cc * HW;

    float acc[2][8][4];
#pragma unroll
    for (int m = 0; m < 2; m++)
#pragma unroll
        for (int t = 0; t < 8; t++)
#pragma unroll
            for (int i = 0; i < 4; i++) acc[m][t][i] = 0.f;

    // A-frag ldsm.trans components
    const int a_ckb = (lid & 7) + (((lid >> 3) & 2) << 2);
    const int a_px8 = (((lid >> 3) & 1) << 3);
    // B-frag components
    const int b_oofs = ((lid >> 4) << 3) + (lid & 7);
    const int b_cg   = ((lid >> 3) & 1);

    // gather mapping: pixel pair + channel half
    const int pp  = tid & 127;       // pixels 2pp, 2pp+1
    const int ckh = tid >> 7;        // 0/1 -> channels ckh*32..+31

    for (int j = 0; j < 9; j++) {
        __syncthreads();
        // stage W chunk: 2048 u32 per buffer
        {
            const uint32_t* whp = (const uint32_t*)g_whi + j * 2048;
            const uint32_t* wlp = (const uint32_t*)g_wlo + j * 2048;
#pragma unroll
            for (int i = 0; i < 8; i++) {
                const int e  = tid + i * 256;
                const int o  = e >> 5;
                const int cg = e & 31;
                const uint32_t off = o * PITCH + cg * 4;
                *(uint32_t*)(smem + T_WHI + off) = __ldg(whp + e);
                *(uint32_t*)(smem + T_WLO + off) = __ldg(wlp + e);
            }
        }
        // private descriptors, hoisted over the 32-channel walk
        const Desc d0 = make_sdesc(n, j, j0 + 2 * pp);
        const Desc d1 = make_sdesc(n, j, j0 + 2 * pp + 1);
        {
            const float* xc = xn + (size_t)(ckh * 32) * HW;
            uint32_t soff = (ckh * 32) * TPITCH2 + pp * 4;
#pragma unroll 8
            for (int i = 0; i < 32; i++) {
                const float v0 = samp(d0, xc);
                const float v1 = samp(d1, xc);
                xc += HW;
                uint32_t hi2, lo2;
                split_pack(v0, v1, hi2, lo2);
                *(uint32_t*)(smem + T_SHI + soff) = hi2;
                *(uint32_t*)(smem + T_SLO + soff) = lo2;
                soff += TPITCH2;
            }
        }
        __syncthreads();

#pragma unroll
        for (int ks = 0; ks < 4; ks++) {
            uint32_t ahi[2][4], alo[2][4];
#pragma unroll
            for (int m = 0; m < 2; m++) {
                const uint32_t aoff = (ks * 16 + a_ckb) * TPITCH2
                                    + (wid * 32 + m * 16 + a_px8) * 2;
                ldsm_x4_t(ahi[m], sbase + T_SHI + aoff);
                ldsm_x4_t(alo[m], sbase + T_SLO + aoff);
            }
#pragma unroll
            for (int nt = 0; nt < 4; nt++) {
                uint32_t bh[4], bl[4];
                const uint32_t boff = (nt * 16 + b_oofs) * PITCH + (ks * 2 + b_cg) * 16;
                ldsm_x4(bh, sbase + T_WHI + boff);
                ldsm_x4(bl, sbase + T_WLO + boff);
#pragma unroll
                for (int m = 0; m < 2; m++) {
                    mma_bf16(acc[m][nt * 2],     ahi[m], bh);
                    mma_bf16(acc[m][nt * 2 + 1], ahi[m], bh + 2);
                    mma_bf16(acc[m][nt * 2],     ahi[m], bl);
                    mma_bf16(acc[m][nt * 2 + 1], ahi[m], bl + 2);
                    mma_bf16(acc[m][nt * 2],     alo[m], bh);
                    mma_bf16(acc[m][nt * 2 + 1], alo[m], bh + 2);
                }
            }
        }
    }

    // Epilogue: D fragments -> out[n][o][pq]
    float* op = out + (size_t)n * COUT * HW;
#pragma unroll
    for (int m = 0; m < 2; m++) {
        const int px = j0 + wid * 32 + m * 16 + (lid >> 2);
#pragma unroll
        for (int t = 0; t < 8; t++) {
            const int o0 = t * 8 + 2 * (lid & 3);
            op[(size_t)o0       * HW + px    ] = acc[m][t][0];
            op[(size_t)(o0 + 1) * HW + px    ] = acc[m][t][1];
            op[(size_t)o0       * HW + px + 8] = acc[m][t][2];
            op[(size_t)(o0 + 1) * HW + px + 8] = acc[m][t][3];
        }
    }
}

// ---------------------------------------------------------------------------
extern "C" void kernel_launch(void* const* d_in, const int* in_sizes, int n_in,
                              void* d_out, int out_size)
{
    const float* x     = (const float*)d_in[0];  // (4,64,128,128)
    const float* w_om  = (const float*)d_in[1];  // (27,64,3,3)
    const float* b_om  = (const float*)d_in[2];  // (27,)
    const float* w_dcn = (const float*)d_in[3];  // (64,64,3,3)
    float* out = (float*)d_out;                  // (4,64,128,128)

    wprep_kernel<<<(WPREP_TOT + 255) / 256, 256>>>(w_dcn, w_om);

    dim3 gA(Hh, 1, Nn);                          // 512 blocks
    convA_mma_kernel<<<gA, 256>>>(x, b_om);

    cudaFuncSetAttribute(fusedBC_mma_kernel,
                         cudaFuncAttributeMaxDynamicSharedMemorySize, T_TOTAL);
    dim3 gBC(HW / 256, 1, Nn);                   // 64 x 4 = 256 blocks
    fusedBC_mma_kernel<<<gBC, 256, T_TOTAL>>>(x, out);
}